// round 6
// baseline (speedup 1.0000x reference)
#include <cuda_runtime.h>
#include <cuda_bf16.h>

#define Bsz  512
#define Ssz  1024
#define Esz  48
#define Hsz  128
#define NCLS 2000
#define BC   4              // batch rows per CTA
#define KPC  26             // cached k-pairs (k < 52 in smem)
#define NKP  64             // total k-pairs
#define NSP  (NKP - KPC)    // streamed k-pairs = 38
#define EP   24             // e-pairs
#define QD   16             // streamed prefetch queue depth (float4)

// Packed parameter storage (prepared once per launch by prep_kernel).
// g_wKpack: [gp][kp][j][q]  q = (gate_lo_k, gate_lo_k+1, gate_hi_k, gate_hi_k+1)
// g_wIK   : [gp][ep][j][q]  same, e = 2*ep
// g_bias  : [gp][j][gi]     (= b_ih + b_hh)
__device__ float g_wKpack[2 * NKP * Hsz * 4];
__device__ float g_wIK   [2 * EP  * Hsz * 4];
__device__ float g_bias  [2 * Hsz * 2];
__device__ float g_wfcT  [Hsz * NCLS];
__device__ float g_hfin  [Bsz * Hsz];

typedef unsigned long long ull;

__device__ __forceinline__ void ffma2(ull& acc, ull a, ull b) {
    asm("fma.rn.f32x2 %0, %1, %2, %0;" : "+l"(acc) : "l"(a), "l"(b));
}
__device__ __forceinline__ ull f2u2(float x, float y) {
    ull r; asm("mov.b64 %0, {%1, %2};" : "=l"(r) : "f"(x), "f"(y)); return r;
}
__device__ __forceinline__ float2 u2f(ull v) {
    float2 r; asm("mov.b64 {%0, %1}, %2;" : "=f"(r.x), "=f"(r.y) : "l"(v)); return r;
}
__device__ __forceinline__ float sigf(float x) {
    return __fdividef(1.0f, 1.0f + __expf(-x));
}
__device__ __forceinline__ float tanf_(float x) {
    float e = __expf(-2.0f * x);
    return __fdividef(1.0f - e, 1.0f + e);
}

// ---------------------------------------------------------------------------
__global__ void prep_kernel(const float* __restrict__ w_ih, const float* __restrict__ w_hh,
                            const float* __restrict__ b_ih, const float* __restrict__ b_hh,
                            const float* __restrict__ w_fc) {
    int i = blockIdx.x * blockDim.x + threadIdx.x;
    if (i < 2 * NKP * Hsz * 4) {
        int q = i & 3, j = (i >> 2) & 127, kp = (i >> 9) & 63, gp = (i >> 15) & 1;
        int gate = gp * 2 + (q >> 1);
        int k = kp * 2 + (q & 1);
        g_wKpack[i] = w_hh[(gate * Hsz + j) * Hsz + k];
    }
    if (i < 2 * EP * Hsz * 4) {
        int q = i & 3, j = (i >> 2) & 127;
        int rest = i >> 9;                 // [0, 48)
        int ep = rest % EP, gp = rest / EP;
        int gate = gp * 2 + (q >> 1);
        int e = ep * 2 + (q & 1);
        g_wIK[i] = w_ih[(gate * Hsz + j) * Esz + e];
    }
    if (i < 2 * Hsz * 2) {
        int gi = i & 1, j = (i >> 1) & 127, gp = i >> 8;
        int r = (gp * 2 + gi) * Hsz + j;
        g_bias[i] = b_ih[r] + b_hh[r];
    }
    if (i < Hsz * NCLS) {
        int k = i / NCLS, n = i % NCLS;
        g_wfcT[i] = w_fc[n * Hsz + k];
    }
}

// ---------------------------------------------------------------------------
// LSTM recurrence. Thread (gp, j): gates (2gp, 2gp+1) x 4 batches.
// f32x2 packed along k: acc lanes = (sum over even k, sum over odd k).
// ---------------------------------------------------------------------------
struct alignas(16) Smem {
    float  wih[2 * EP  * Hsz * 4];   //  96 KB
    float  whh[2 * KPC * Hsz * 4];   // 104 KB (k-pairs < KPC)
    float  h[BC][Hsz];               //   2 KB
    float  c[BC][Hsz];               //   2 KB
    float2 gbuf[2][BC][Hsz];         //   8 KB  [gp][bc][j] = (g_2gp, g_2gp+1)
    float  e[2][BC][Esz];            // 1.5 KB  double-buffered embeddings
};

struct Acc8 {
    ull a00, a01, a02, a03, a10, a11, a12, a13;
};

__device__ __forceinline__ void kp2(Acc8& A, float4 w, ull o0, ull o1, ull o2, ull o3) {
    const ull pA = f2u2(w.x, w.y);
    const ull pB = f2u2(w.z, w.w);
    ffma2(A.a00, pA, o0); ffma2(A.a01, pA, o1);
    ffma2(A.a02, pA, o2); ffma2(A.a03, pA, o3);
    ffma2(A.a10, pB, o0); ffma2(A.a11, pB, o1);
    ffma2(A.a12, pB, o2); ffma2(A.a13, pB, o3);
}

__global__ void __launch_bounds__(256, 1)
lstm_kernel(const int* __restrict__ x, const float* __restrict__ emb) {
    extern __shared__ char smem_raw[];
    Smem* s = reinterpret_cast<Smem*>(smem_raw);

    const int tid = threadIdx.x;
    const int j   = tid & 127;
    const int gp  = tid >> 7;
    const int b0  = blockIdx.x * BC;

    // Stage packed weights into smem.
    for (int i = tid; i < 2 * EP * Hsz * 4; i += 256) s->wih[i] = g_wIK[i];
    for (int g = 0; g < 2; g++)
        for (int i = tid; i < KPC * Hsz * 4; i += 256)
            s->whh[g * (KPC * 512) + i] = g_wKpack[g * (NKP * 512) + i];
    for (int i = tid; i < BC * Hsz; i += 256) {
        s->h[i >> 7][i & 127] = 0.0f;
        s->c[i >> 7][i & 127] = 0.0f;
    }
    __syncthreads();

    // Embedding prefetch lanes: 192 threads, one (bc, e) element each.
    const int  bcp = tid / Esz;
    const int  eep = tid - bcp * Esz;
    const bool eTh = (tid < BC * Esz);
    int tv = 0;
    if (eTh) {
        const int t0 = __ldg(&x[(b0 + bcp) * Ssz + 0]);
        s->e[0][bcp][eep] = __ldg(&emb[t0 * Esz + eep]);
        tv = __ldg(&x[(b0 + bcp) * Ssz + 1]);
    }

    const float2 b2 = *(const float2*)(g_bias + (gp * Hsz + j) * 2);
    const ull bias0 = f2u2(b2.x, 0.0f);
    const ull bias1 = f2u2(b2.y, 0.0f);
    const float* __restrict__ wcH = s->whh    + gp * (KPC * 512) + j * 4;
    const float* __restrict__ wgH = g_wKpack  + (gp * NKP + KPC) * 512 + j * 4;
    const float* __restrict__ wcI = s->wih    + gp * (EP * 512) + j * 4;

    // Persistent streamed-weight prefetch queue: first QD k-pairs in flight
    // before the loop; refilled for step t+1 during step t's combine phase.
    float4 wq[QD];
    #pragma unroll
    for (int q = 0; q < QD; q++)
        wq[q] = *(const float4*)(wgH + q * 512);
    __syncthreads();

    for (int st = 0; st < Ssz; st++) {
        const int buf = st & 1;

        // Prefetch next step's embedding row + token after that.
        float ev = 0.0f;
        const bool doE = eTh && (st + 1 < Ssz);
        if (doE) ev = __ldg(&emb[tv * Esz + eep]);
        int tvn = 0;
        if (eTh && (st + 2 < Ssz)) tvn = __ldg(&x[(b0 + bcp) * Ssz + st + 2]);

        Acc8 A;
        A.a00 = bias0; A.a01 = bias0; A.a02 = bias0; A.a03 = bias0;
        A.a10 = bias1; A.a11 = bias1; A.a12 = bias1; A.a13 = bias1;

        // --- recurrent GEMV, smem-cached k-pairs [0, KPC) ---
        #pragma unroll
        for (int g2 = 0; g2 < KPC / 2; g2++) {
            const ulonglong2 h0 = *(const ulonglong2*)&s->h[0][g2 * 4];
            const ulonglong2 h1 = *(const ulonglong2*)&s->h[1][g2 * 4];
            const ulonglong2 h2 = *(const ulonglong2*)&s->h[2][g2 * 4];
            const ulonglong2 h3 = *(const ulonglong2*)&s->h[3][g2 * 4];
            const float4 wA = *(const float4*)(wcH + (2 * g2 + 0) * 512);
            const float4 wB = *(const float4*)(wcH + (2 * g2 + 1) * 512);
            kp2(A, wA, h0.x, h1.x, h2.x, h3.x);
            kp2(A, wB, h0.y, h1.y, h2.y, h3.y);
        }

        // --- input GEMV (fused embedding), e-pairs in smem ---
        #pragma unroll
        for (int g2 = 0; g2 < EP / 2; g2++) {
            const ulonglong2 e0 = *(const ulonglong2*)&s->e[buf][0][g2 * 4];
            const ulonglong2 e1 = *(const ulonglong2*)&s->e[buf][1][g2 * 4];
            const ulonglong2 e2 = *(const ulonglong2*)&s->e[buf][2][g2 * 4];
            const ulonglong2 e3 = *(const ulonglong2*)&s->e[buf][3][g2 * 4];
            const float4 wA = *(const float4*)(wcI + (2 * g2 + 0) * 512);
            const float4 wB = *(const float4*)(wcI + (2 * g2 + 1) * 512);
            kp2(A, wA, e0.x, e1.x, e2.x, e3.x);
            kp2(A, wB, e0.y, e1.y, e2.y, e3.y);
        }

        // --- recurrent GEMV, L2-streamed k-pairs [KPC, 64) ---
        // Queue holds kp..kp+QD-1; rolling prefetch keeps distance QD (>=350cyc).
        #pragma unroll
        for (int t = 0; t < NSP / 2; t++) {          // 19 groups of 2 k-pairs
            const int kp = 2 * t;
            const ulonglong2 h0 = *(const ulonglong2*)&s->h[0][2 * KPC + t * 4];
            const ulonglong2 h1 = *(const ulonglong2*)&s->h[1][2 * KPC + t * 4];
            const ulonglong2 h2 = *(const ulonglong2*)&s->h[2][2 * KPC + t * 4];
            const ulonglong2 h3 = *(const ulonglong2*)&s->h[3][2 * KPC + t * 4];
            const float4 wA = wq[(kp + 0) % QD];
            const float4 wB = wq[(kp + 1) % QD];
            if (kp + QD < NSP)
                wq[(kp + 0) % QD] = *(const float4*)(wgH + (kp + QD) * 512);
            if (kp + QD + 1 < NSP)
                wq[(kp + 1) % QD] = *(const float4*)(wgH + (kp + QD + 1) * 512);
            kp2(A, wA, h0.x, h1.x, h2.x, h3.x);
            kp2(A, wB, h0.y, h1.y, h2.y, h3.y);
        }

        // Publish pre-activations: gate value = lane.x + lane.y.
        {
            const float2 r00 = u2f(A.a00), r01 = u2f(A.a01), r02 = u2f(A.a02), r03 = u2f(A.a03);
            const float2 r10 = u2f(A.a10), r11 = u2f(A.a11), r12 = u2f(A.a12), r13 = u2f(A.a13);
            s->gbuf[gp][0][j] = make_float2(r00.x + r00.y, r10.x + r10.y);
            s->gbuf[gp][1][j] = make_float2(r01.x + r01.y, r11.x + r11.y);
            s->gbuf[gp][2][j] = make_float2(r02.x + r02.y, r12.x + r12.y);
            s->gbuf[gp][3][j] = make_float2(r03.x + r03.y, r13.x + r13.y);
        }
        __syncthreads();

        // Refill the queue for NEXT step now: these LDGs fly during the
        // combine + barrier + next step's cached/input sections.
        #pragma unroll
        for (int q = 0; q < QD; q++)
            wq[q] = *(const float4*)(wgH + q * 512);

        // Gate combine: 512 cells over 256 threads, 2 each.
        #pragma unroll
        for (int r = 0; r < 2; r++) {
            const int idx = tid + r * 256;
            const int bc = idx >> 7, jj = idx & 127;
            const float2 gif = s->gbuf[0][bc][jj];   // (i, f)
            const float2 ggo = s->gbuf[1][bc][jj];   // (g, o)
            const float iv = sigf(gif.x);
            const float fv = sigf(gif.y);
            const float gv = tanf_(ggo.x);
            const float ov = sigf(ggo.y);
            const float cv = fv * s->c[bc][jj] + iv * gv;
            s->c[bc][jj] = cv;
            s->h[bc][jj] = ov * tanf_(cv);
        }
        if (doE) s->e[buf ^ 1][bcp][eep] = ev;
        tv = tvn;
        __syncthreads();
    }

    // Export final hidden state.
    for (int i = tid; i < BC * Hsz; i += 256)
        g_hfin[(b0 + (i >> 7)) * Hsz + (i & 127)] = s->h[i >> 7][i & 127];
}

// ---------------------------------------------------------------------------
// FC epilogue: out[b][n] = h_fin[b] . w_fc[n] + b_fc[n]
// ---------------------------------------------------------------------------
__global__ void fc_kernel(const float* __restrict__ b_fc, float* __restrict__ out) {
    __shared__ float hs[8][Hsz];
    const int tid = threadIdx.x;
    const int n   = blockIdx.x * 128 + tid;
    const int bb  = blockIdx.y * 8;
    for (int i = tid; i < 8 * Hsz; i += 128)
        hs[i >> 7][i & 127] = g_hfin[(bb + (i >> 7)) * Hsz + (i & 127)];
    __syncthreads();
    if (n >= NCLS) return;
    const float bv = b_fc[n];
    float acc[8];
    #pragma unroll
    for (int i = 0; i < 8; i++) acc[i] = bv;
    #pragma unroll 4
    for (int k = 0; k < Hsz; k++) {
        const float w = g_wfcT[k * NCLS + n];
        #pragma unroll
        for (int i = 0; i < 8; i++) acc[i] = fmaf(hs[i][k], w, acc[i]);
    }
    #pragma unroll
    for (int i = 0; i < 8; i++) out[(bb + i) * NCLS + n] = acc[i];
}

extern "C" void kernel_launch(void* const* d_in, const int* in_sizes, int n_in,
                              void* d_out, int out_size) {
    const int*   x    = (const int*)  d_in[0];
    const float* emb  = (const float*)d_in[1];
    const float* w_ih = (const float*)d_in[2];
    const float* w_hh = (const float*)d_in[3];
    const float* b_ih = (const float*)d_in[4];
    const float* b_hh = (const float*)d_in[5];
    const float* w_fc = (const float*)d_in[6];
    const float* b_fc = (const float*)d_in[7];
    float* out = (float*)d_out;

    static bool attr_set = false;
    if (!attr_set) {
        cudaFuncSetAttribute(lstm_kernel, cudaFuncAttributeMaxDynamicSharedMemorySize,
                             (int)sizeof(Smem));
        attr_set = true;
    }

    prep_kernel<<<1000, 256>>>(w_ih, w_hh, b_ih, b_hh, w_fc);
    lstm_kernel<<<Bsz / BC, 256, sizeof(Smem)>>>(x, emb);
    fc_kernel<<<dim3((NCLS + 127) / 128, Bsz / 8), 128>>>(b_fc, out);
}

// round 7
// speedup vs baseline: 1.2709x; 1.2709x over previous
#include <cuda_runtime.h>
#include <cuda_bf16.h>

#define Bsz  512
#define Ssz  1024
#define Esz  48
#define Hsz  128
#define NCLS 2000
#define BC   4              // batch rows per CTA
#define NKP  64             // total k-pairs
#define SPK  20             // k-pairs held in smem   (kp 0..19)
#define RPK  44             // k-pairs held in REGISTERS (kp 20..63)
#define EP   24             // e-pairs (all in smem)

// Packed parameter storage (prepared once per launch by prep_kernel).
// g_wKpack: [gp][kp][j][q]  q = (gate_lo_k, gate_lo_k+1, gate_hi_k, gate_hi_k+1)
// g_wIK   : [gp][ep][j][q]
// g_bias  : [gp][j][gi]     (= b_ih + b_hh)
__device__ float g_wKpack[2 * NKP * Hsz * 4];
__device__ float g_wIK   [2 * EP  * Hsz * 4];
__device__ float g_bias  [2 * Hsz * 2];
__device__ float g_wfcT  [Hsz * NCLS];
__device__ float g_hfin  [Bsz * Hsz];

typedef unsigned long long ull;

__device__ __forceinline__ void ffma2(ull& acc, ull a, ull b) {
    asm("fma.rn.f32x2 %0, %1, %2, %0;" : "+l"(acc) : "l"(a), "l"(b));
}
__device__ __forceinline__ ull f2u2(float x, float y) {
    ull r; asm("mov.b64 %0, {%1, %2};" : "=l"(r) : "f"(x), "f"(y)); return r;
}
__device__ __forceinline__ float2 u2f(ull v) {
    float2 r; asm("mov.b64 {%0, %1}, %2;" : "=f"(r.x), "=f"(r.y) : "l"(v)); return r;
}
__device__ __forceinline__ float sigf(float x) {
    return __fdividef(1.0f, 1.0f + __expf(-x));
}
__device__ __forceinline__ float tanf_(float x) {
    float e = __expf(-2.0f * x);
    return __fdividef(1.0f - e, 1.0f + e);
}

// ---------------------------------------------------------------------------
__global__ void prep_kernel(const float* __restrict__ w_ih, const float* __restrict__ w_hh,
                            const float* __restrict__ b_ih, const float* __restrict__ b_hh,
                            const float* __restrict__ w_fc) {
    int i = blockIdx.x * blockDim.x + threadIdx.x;
    if (i < 2 * NKP * Hsz * 4) {
        int q = i & 3, j = (i >> 2) & 127, kp = (i >> 9) & 63, gp = (i >> 15) & 1;
        int gate = gp * 2 + (q >> 1);
        int k = kp * 2 + (q & 1);
        g_wKpack[i] = w_hh[(gate * Hsz + j) * Hsz + k];
    }
    if (i < 2 * EP * Hsz * 4) {
        int q = i & 3, j = (i >> 2) & 127;
        int rest = i >> 9;                 // [0, 48)
        int ep = rest % EP, gp = rest / EP;
        int gate = gp * 2 + (q >> 1);
        int e = ep * 2 + (q & 1);
        g_wIK[i] = w_ih[(gate * Hsz + j) * Esz + e];
    }
    if (i < 2 * Hsz * 2) {
        int gi = i & 1, j = (i >> 1) & 127, gp = i >> 8;
        int r = (gp * 2 + gi) * Hsz + j;
        g_bias[i] = b_ih[r] + b_hh[r];
    }
    if (i < Hsz * NCLS) {
        int k = i / NCLS, n = i % NCLS;
        g_wfcT[i] = w_fc[n * Hsz + k];
    }
}

// ---------------------------------------------------------------------------
// LSTM recurrence, persistent-RNN style: 176 weight registers per thread.
// Thread (gp, j): gates (2gp, 2gp+1) x 4 batches.
// f32x2 packed along k: acc lanes = (sum over even k, sum over odd k).
// ---------------------------------------------------------------------------
struct alignas(16) Smem {
    float  wih[2 * EP  * Hsz * 4];   //  96 KB (all e-pairs)
    float  whh[2 * SPK * Hsz * 4];   //  80 KB (k-pairs 0..SPK-1)
    float  h[BC][Hsz];               //   2 KB
    float  c[BC][Hsz];               //   2 KB
    float2 gbuf[2][BC][Hsz];         //   8 KB  [gp][bc][j] = (g_2gp, g_2gp+1)
    float  e[2][BC][Esz];            // 1.5 KB  double-buffered embeddings
};

struct Acc8 {
    ull a00, a01, a02, a03, a10, a11, a12, a13;
};

__device__ __forceinline__ void kp2(Acc8& A, float4 w, ull o0, ull o1, ull o2, ull o3) {
    const ull pA = f2u2(w.x, w.y);
    const ull pB = f2u2(w.z, w.w);
    ffma2(A.a00, pA, o0); ffma2(A.a01, pA, o1);
    ffma2(A.a02, pA, o2); ffma2(A.a03, pA, o3);
    ffma2(A.a10, pB, o0); ffma2(A.a11, pB, o1);
    ffma2(A.a12, pB, o2); ffma2(A.a13, pB, o3);
}

__global__ void __launch_bounds__(256, 1)
lstm_kernel(const int* __restrict__ x, const float* __restrict__ emb) {
    extern __shared__ char smem_raw[];
    Smem* s = reinterpret_cast<Smem*>(smem_raw);

    const int tid = threadIdx.x;
    const int j   = tid & 127;
    const int gp  = tid >> 7;
    const int b0  = blockIdx.x * BC;

    // Stage smem-resident weights.
    for (int i = tid; i < 2 * EP * Hsz * 4; i += 256) s->wih[i] = g_wIK[i];
    for (int g = 0; g < 2; g++)
        for (int i = tid; i < SPK * Hsz * 4; i += 256)
            s->whh[g * (SPK * 512) + i] = g_wKpack[g * (NKP * 512) + i];
    for (int i = tid; i < BC * Hsz; i += 256) {
        s->h[i >> 7][i & 127] = 0.0f;
        s->c[i >> 7][i & 127] = 0.0f;
    }

    // Load this thread's REGISTER-RESIDENT weights: k-pairs SPK..NKP-1.
    float4 wreg[RPK];
    {
        const float4* __restrict__ src =
            (const float4*)(g_wKpack + (gp * NKP + SPK) * 512 + j * 4);
        #pragma unroll
        for (int r = 0; r < RPK; r++)
            wreg[r] = src[r * 128];          // stride 512 floats = 128 float4
    }
    __syncthreads();

    // Embedding prefetch lanes: 192 threads, one (bc, e) element each.
    const int  bcp = tid / Esz;
    const int  eep = tid - bcp * Esz;
    const bool eTh = (tid < BC * Esz);
    int tv = 0;
    if (eTh) {
        const int t0 = __ldg(&x[(b0 + bcp) * Ssz + 0]);
        s->e[0][bcp][eep] = __ldg(&emb[t0 * Esz + eep]);
        tv = __ldg(&x[(b0 + bcp) * Ssz + 1]);
    }

    const float2 b2 = *(const float2*)(g_bias + (gp * Hsz + j) * 2);
    const ull bias0 = f2u2(b2.x, 0.0f);
    const ull bias1 = f2u2(b2.y, 0.0f);
    const float* __restrict__ wcH = s->whh + gp * (SPK * 512) + j * 4;
    const float* __restrict__ wcI = s->wih + gp * (EP  * 512) + j * 4;
    __syncthreads();

    for (int st = 0; st < Ssz; st++) {
        const int buf = st & 1;

        // Prefetch next step's embedding row + token after that.
        float ev = 0.0f;
        const bool doE = eTh && (st + 1 < Ssz);
        if (doE) ev = __ldg(&emb[tv * Esz + eep]);
        int tvn = 0;
        if (eTh && (st + 2 < Ssz)) tvn = __ldg(&x[(b0 + bcp) * Ssz + st + 2]);

        Acc8 A;
        A.a00 = bias0; A.a01 = bias0; A.a02 = bias0; A.a03 = bias0;
        A.a10 = bias1; A.a11 = bias1; A.a12 = bias1; A.a13 = bias1;

        // --- recurrent GEMV, REGISTER k-pairs [SPK, NKP): only h broadcasts ---
        #pragma unroll
        for (int r2 = 0; r2 < RPK / 2; r2++) {
            const int hofs = 2 * SPK + r2 * 4;
            const ulonglong2 h0 = *(const ulonglong2*)&s->h[0][hofs];
            const ulonglong2 h1 = *(const ulonglong2*)&s->h[1][hofs];
            const ulonglong2 h2 = *(const ulonglong2*)&s->h[2][hofs];
            const ulonglong2 h3 = *(const ulonglong2*)&s->h[3][hofs];
            kp2(A, wreg[2 * r2 + 0], h0.x, h1.x, h2.x, h3.x);
            kp2(A, wreg[2 * r2 + 1], h0.y, h1.y, h2.y, h3.y);
        }

        // --- recurrent GEMV, smem k-pairs [0, SPK) ---
        #pragma unroll
        for (int g2 = 0; g2 < SPK / 2; g2++) {
            const ulonglong2 h0 = *(const ulonglong2*)&s->h[0][g2 * 4];
            const ulonglong2 h1 = *(const ulonglong2*)&s->h[1][g2 * 4];
            const ulonglong2 h2 = *(const ulonglong2*)&s->h[2][g2 * 4];
            const ulonglong2 h3 = *(const ulonglong2*)&s->h[3][g2 * 4];
            const float4 wA = *(const float4*)(wcH + (2 * g2 + 0) * 512);
            const float4 wB = *(const float4*)(wcH + (2 * g2 + 1) * 512);
            kp2(A, wA, h0.x, h1.x, h2.x, h3.x);
            kp2(A, wB, h0.y, h1.y, h2.y, h3.y);
        }

        // --- input GEMV (fused embedding), e-pairs in smem ---
        #pragma unroll
        for (int g2 = 0; g2 < EP / 2; g2++) {
            const ulonglong2 e0 = *(const ulonglong2*)&s->e[buf][0][g2 * 4];
            const ulonglong2 e1 = *(const ulonglong2*)&s->e[buf][1][g2 * 4];
            const ulonglong2 e2 = *(const ulonglong2*)&s->e[buf][2][g2 * 4];
            const ulonglong2 e3 = *(const ulonglong2*)&s->e[buf][3][g2 * 4];
            const float4 wA = *(const float4*)(wcI + (2 * g2 + 0) * 512);
            const float4 wB = *(const float4*)(wcI + (2 * g2 + 1) * 512);
            kp2(A, wA, e0.x, e1.x, e2.x, e3.x);
            kp2(A, wB, e0.y, e1.y, e2.y, e3.y);
        }

        // Publish pre-activations: gate value = lane.x + lane.y.
        {
            const float2 r00 = u2f(A.a00), r01 = u2f(A.a01), r02 = u2f(A.a02), r03 = u2f(A.a03);
            const float2 r10 = u2f(A.a10), r11 = u2f(A.a11), r12 = u2f(A.a12), r13 = u2f(A.a13);
            s->gbuf[gp][0][j] = make_float2(r00.x + r00.y, r10.x + r10.y);
            s->gbuf[gp][1][j] = make_float2(r01.x + r01.y, r11.x + r11.y);
            s->gbuf[gp][2][j] = make_float2(r02.x + r02.y, r12.x + r12.y);
            s->gbuf[gp][3][j] = make_float2(r03.x + r03.y, r13.x + r13.y);
        }
        __syncthreads();

        // Gate combine: 512 cells over 256 threads, 2 each.
        #pragma unroll
        for (int r = 0; r < 2; r++) {
            const int idx = tid + r * 256;
            const int bc = idx >> 7, jj = idx & 127;
            const float2 gif = s->gbuf[0][bc][jj];   // (i, f)
            const float2 ggo = s->gbuf[1][bc][jj];   // (g, o)
            const float iv = sigf(gif.x);
            const float fv = sigf(gif.y);
            const float gv = tanf_(ggo.x);
            const float ov = sigf(ggo.y);
            const float cv = fv * s->c[bc][jj] + iv * gv;
            s->c[bc][jj] = cv;
            s->h[bc][jj] = ov * tanf_(cv);
        }
        if (doE) s->e[buf ^ 1][bcp][eep] = ev;
        tv = tvn;
        __syncthreads();
    }

    // Export final hidden state.
    for (int i = tid; i < BC * Hsz; i += 256)
        g_hfin[(b0 + (i >> 7)) * Hsz + (i & 127)] = s->h[i >> 7][i & 127];
}

// ---------------------------------------------------------------------------
// FC epilogue: out[b][n] = h_fin[b] . w_fc[n] + b_fc[n]
// ---------------------------------------------------------------------------
__global__ void fc_kernel(const float* __restrict__ b_fc, float* __restrict__ out) {
    __shared__ float hs[8][Hsz];
    const int tid = threadIdx.x;
    const int n   = blockIdx.x * 128 + tid;
    const int bb  = blockIdx.y * 8;
    for (int i = tid; i < 8 * Hsz; i += 128)
        hs[i >> 7][i & 127] = g_hfin[(bb + (i >> 7)) * Hsz + (i & 127)];
    __syncthreads();
    if (n >= NCLS) return;
    const float bv = b_fc[n];
    float acc[8];
    #pragma unroll
    for (int i = 0; i < 8; i++) acc[i] = bv;
    #pragma unroll 4
    for (int k = 0; k < Hsz; k++) {
        const float w = g_wfcT[k * NCLS + n];
        #pragma unroll
        for (int i = 0; i < 8; i++) acc[i] = fmaf(hs[i][k], w, acc[i]);
    }
    #pragma unroll
    for (int i = 0; i < 8; i++) out[(bb + i) * NCLS + n] = acc[i];
}

extern "C" void kernel_launch(void* const* d_in, const int* in_sizes, int n_in,
                              void* d_out, int out_size) {
    const int*   x    = (const int*)  d_in[0];
    const float* emb  = (const float*)d_in[1];
    const float* w_ih = (const float*)d_in[2];
    const float* w_hh = (const float*)d_in[3];
    const float* b_ih = (const float*)d_in[4];
    const float* b_hh = (const float*)d_in[5];
    const float* w_fc = (const float*)d_in[6];
    const float* b_fc = (const float*)d_in[7];
    float* out = (float*)d_out;

    static bool attr_set = false;
    if (!attr_set) {
        cudaFuncSetAttribute(lstm_kernel, cudaFuncAttributeMaxDynamicSharedMemorySize,
                             (int)sizeof(Smem));
        attr_set = true;
    }

    prep_kernel<<<1000, 256>>>(w_ih, w_hh, b_ih, b_hh, w_fc);
    lstm_kernel<<<Bsz / BC, 256, sizeof(Smem)>>>(x, emb);
    fc_kernel<<<dim3((NCLS + 127) / 128, Bsz / 8), 128>>>(b_fc, out);
}

// round 8
// speedup vs baseline: 1.2711x; 1.0001x over previous
#include <cuda_runtime.h>
#include <cuda_bf16.h>

#define Bsz  512
#define Ssz  1024
#define Esz  48
#define Hsz  128
#define NCLS 2000
#define BC   4              // batch rows per CTA
#define NKP  64             // total k-pairs
#define SPK  20             // k-pairs held in smem   (kp 0..19)
#define RPK  44             // k-pairs held in REGISTERS (kp 20..63)
#define EP   24             // e-pairs (all in smem)

// Packed parameter storage (prepared once per launch by prep_kernel).
// g_wKpack: [gp][kp][j][q]  q = (gate_lo_k, gate_lo_k+1, gate_hi_k, gate_hi_k+1)
// g_wIK   : [gp][ep][j][q]
// g_bias  : [gp][j][gi]     (= b_ih + b_hh)
__device__ float g_wKpack[2 * NKP * Hsz * 4];
__device__ float g_wIK   [2 * EP  * Hsz * 4];
__device__ float g_bias  [2 * Hsz * 2];
__device__ float g_wfcT  [Hsz * NCLS];
__device__ float g_hfin  [Bsz * Hsz];

typedef unsigned long long ull;

__device__ __forceinline__ void ffma2(ull& acc, ull a, ull b) {
    asm("fma.rn.f32x2 %0, %1, %2, %0;" : "+l"(acc) : "l"(a), "l"(b));
}
__device__ __forceinline__ ull f2u2(float x, float y) {
    ull r; asm("mov.b64 %0, {%1, %2};" : "=l"(r) : "f"(x), "f"(y)); return r;
}
__device__ __forceinline__ float2 u2f(ull v) {
    float2 r; asm("mov.b64 {%0, %1}, %2;" : "=f"(r.x), "=f"(r.y) : "l"(v)); return r;
}
__device__ __forceinline__ float sigf(float x) {
    return __fdividef(1.0f, 1.0f + __expf(-x));
}
__device__ __forceinline__ float tanf_(float x) {
    float e = __expf(-2.0f * x);
    return __fdividef(1.0f - e, 1.0f + e);
}

// ---------------------------------------------------------------------------
__global__ void prep_kernel(const float* __restrict__ w_ih, const float* __restrict__ w_hh,
                            const float* __restrict__ b_ih, const float* __restrict__ b_hh,
                            const float* __restrict__ w_fc) {
    int i = blockIdx.x * blockDim.x + threadIdx.x;
    if (i < 2 * NKP * Hsz * 4) {
        int q = i & 3, j = (i >> 2) & 127, kp = (i >> 9) & 63, gp = (i >> 15) & 1;
        int gate = gp * 2 + (q >> 1);
        int k = kp * 2 + (q & 1);
        g_wKpack[i] = w_hh[(gate * Hsz + j) * Hsz + k];
    }
    if (i < 2 * EP * Hsz * 4) {
        int q = i & 3, j = (i >> 2) & 127;
        int rest = i >> 9;                 // [0, 48)
        int ep = rest % EP, gp = rest / EP;
        int gate = gp * 2 + (q >> 1);
        int e = ep * 2 + (q & 1);
        g_wIK[i] = w_ih[(gate * Hsz + j) * Esz + e];
    }
    if (i < 2 * Hsz * 2) {
        int gi = i & 1, j = (i >> 1) & 127, gp = i >> 8;
        int r = (gp * 2 + gi) * Hsz + j;
        g_bias[i] = b_ih[r] + b_hh[r];
    }
    if (i < Hsz * NCLS) {
        int k = i / NCLS, n = i % NCLS;
        g_wfcT[i] = w_fc[n * Hsz + k];
    }
}

// ---------------------------------------------------------------------------
// LSTM recurrence, persistent-RNN style: 176 weight registers per thread,
// with a distance-1 software pipeline on the h/e broadcast operands.
// Thread (gp, j): gates (2gp, 2gp+1) x 4 batches.
// ---------------------------------------------------------------------------
struct alignas(16) Smem {
    float  wih[2 * EP  * Hsz * 4];   //  96 KB (all e-pairs)
    float  whh[2 * SPK * Hsz * 4];   //  80 KB (k-pairs 0..SPK-1)
    float  h[BC][Hsz];               //   2 KB
    float  c[BC][Hsz];               //   2 KB
    float2 gbuf[2][BC][Hsz];         //   8 KB  [gp][bc][j] = (g_2gp, g_2gp+1)
    float  e[2][BC][Esz];            // 1.5 KB  double-buffered embeddings
};

struct Acc8 {
    ull a00, a01, a02, a03, a10, a11, a12, a13;
};
struct Op4 {                          // one group's operands: 4 batches x 2 k-pairs
    ulonglong2 v0, v1, v2, v3;
};

__device__ __forceinline__ void kp2(Acc8& A, float4 w, ull o0, ull o1, ull o2, ull o3) {
    const ull pA = f2u2(w.x, w.y);
    const ull pB = f2u2(w.z, w.w);
    ffma2(A.a00, pA, o0); ffma2(A.a01, pA, o1);
    ffma2(A.a02, pA, o2); ffma2(A.a03, pA, o3);
    ffma2(A.a10, pB, o0); ffma2(A.a11, pB, o1);
    ffma2(A.a12, pB, o2); ffma2(A.a13, pB, o3);
}

__global__ void __launch_bounds__(256, 1)
lstm_kernel(const int* __restrict__ x, const float* __restrict__ emb) {
    extern __shared__ char smem_raw[];
    Smem* s = reinterpret_cast<Smem*>(smem_raw);

    const int tid = threadIdx.x;
    const int j   = tid & 127;
    const int gp  = tid >> 7;
    const int b0  = blockIdx.x * BC;

    // Stage smem-resident weights.
    for (int i = tid; i < 2 * EP * Hsz * 4; i += 256) s->wih[i] = g_wIK[i];
    for (int g = 0; g < 2; g++)
        for (int i = tid; i < SPK * Hsz * 4; i += 256)
            s->whh[g * (SPK * 512) + i] = g_wKpack[g * (NKP * 512) + i];
    for (int i = tid; i < BC * Hsz; i += 256) {
        s->h[i >> 7][i & 127] = 0.0f;
        s->c[i >> 7][i & 127] = 0.0f;
    }

    // Load this thread's REGISTER-RESIDENT weights: k-pairs SPK..NKP-1.
    float4 wreg[RPK];
    {
        const float4* __restrict__ src =
            (const float4*)(g_wKpack + (gp * NKP + SPK) * 512 + j * 4);
        #pragma unroll
        for (int r = 0; r < RPK; r++)
            wreg[r] = src[r * 128];          // stride 512 floats = 128 float4
    }
    __syncthreads();

    // Embedding prefetch lanes: 192 threads, one (bc, e) element each.
    const int  bcp = tid / Esz;
    const int  eep = tid - bcp * Esz;
    const bool eTh = (tid < BC * Esz);
    int tv = 0;
    if (eTh) {
        const int t0 = __ldg(&x[(b0 + bcp) * Ssz + 0]);
        s->e[0][bcp][eep] = __ldg(&emb[t0 * Esz + eep]);
        tv = __ldg(&x[(b0 + bcp) * Ssz + 1]);
    }

    const float2 b2 = *(const float2*)(g_bias + (gp * Hsz + j) * 2);
    const ull bias0 = f2u2(b2.x, 0.0f);
    const ull bias1 = f2u2(b2.y, 0.0f);
    const float* __restrict__ wcH = s->whh + gp * (SPK * 512) + j * 4;
    const float* __restrict__ wcI = s->wih + gp * (EP  * 512) + j * 4;
    __syncthreads();

    for (int st = 0; st < Ssz; st++) {
        const int buf = st & 1;

        // Prefetch next step's embedding row + token after that.
        float ev = 0.0f;
        const bool doE = eTh && (st + 1 < Ssz);
        if (doE) ev = __ldg(&emb[tv * Esz + eep]);
        int tvn = 0;
        if (eTh && (st + 2 < Ssz)) tvn = __ldg(&x[(b0 + bcp) * Ssz + st + 2]);

        Acc8 A;
        A.a00 = bias0; A.a01 = bias0; A.a02 = bias0; A.a03 = bias0;
        A.a10 = bias1; A.a11 = bias1; A.a12 = bias1; A.a13 = bias1;

        // Operand pipeline: cur = group being consumed, nxt = in flight.
        Op4 cur, nxt;
        // Preload first register-section group (h offset 2*SPK).
        cur.v0 = *(const ulonglong2*)&s->h[0][2 * SPK];
        cur.v1 = *(const ulonglong2*)&s->h[1][2 * SPK];
        cur.v2 = *(const ulonglong2*)&s->h[2][2 * SPK];
        cur.v3 = *(const ulonglong2*)&s->h[3][2 * SPK];

        // --- recurrent GEMV, REGISTER k-pairs [SPK, NKP) ---
        #pragma unroll
        for (int r2 = 0; r2 < RPK / 2; r2++) {
            if (r2 + 1 < RPK / 2) {
                const int hofs = 2 * SPK + (r2 + 1) * 4;
                nxt.v0 = *(const ulonglong2*)&s->h[0][hofs];
                nxt.v1 = *(const ulonglong2*)&s->h[1][hofs];
                nxt.v2 = *(const ulonglong2*)&s->h[2][hofs];
                nxt.v3 = *(const ulonglong2*)&s->h[3][hofs];
            } else {       // first smem-k group (h offset 0)
                nxt.v0 = *(const ulonglong2*)&s->h[0][0];
                nxt.v1 = *(const ulonglong2*)&s->h[1][0];
                nxt.v2 = *(const ulonglong2*)&s->h[2][0];
                nxt.v3 = *(const ulonglong2*)&s->h[3][0];
            }
            kp2(A, wreg[2 * r2 + 0], cur.v0.x, cur.v1.x, cur.v2.x, cur.v3.x);
            kp2(A, wreg[2 * r2 + 1], cur.v0.y, cur.v1.y, cur.v2.y, cur.v3.y);
            cur = nxt;
        }

        // --- recurrent GEMV, smem k-pairs [0, SPK) ---
        #pragma unroll
        for (int g2 = 0; g2 < SPK / 2; g2++) {
            if (g2 + 1 < SPK / 2) {
                const int hofs = (g2 + 1) * 4;
                nxt.v0 = *(const ulonglong2*)&s->h[0][hofs];
                nxt.v1 = *(const ulonglong2*)&s->h[1][hofs];
                nxt.v2 = *(const ulonglong2*)&s->h[2][hofs];
                nxt.v3 = *(const ulonglong2*)&s->h[3][hofs];
            } else {       // first e group
                nxt.v0 = *(const ulonglong2*)&s->e[buf][0][0];
                nxt.v1 = *(const ulonglong2*)&s->e[buf][1][0];
                nxt.v2 = *(const ulonglong2*)&s->e[buf][2][0];
                nxt.v3 = *(const ulonglong2*)&s->e[buf][3][0];
            }
            const float4 wA = *(const float4*)(wcH + (2 * g2 + 0) * 512);
            const float4 wB = *(const float4*)(wcH + (2 * g2 + 1) * 512);
            kp2(A, wA, cur.v0.x, cur.v1.x, cur.v2.x, cur.v3.x);
            kp2(A, wB, cur.v0.y, cur.v1.y, cur.v2.y, cur.v3.y);
            cur = nxt;
        }

        // --- input GEMV (fused embedding), e-pairs in smem ---
        #pragma unroll
        for (int g2 = 0; g2 < EP / 2; g2++) {
            if (g2 + 1 < EP / 2) {
                const int eofs = (g2 + 1) * 4;
                nxt.v0 = *(const ulonglong2*)&s->e[buf][0][eofs];
                nxt.v1 = *(const ulonglong2*)&s->e[buf][1][eofs];
                nxt.v2 = *(const ulonglong2*)&s->e[buf][2][eofs];
                nxt.v3 = *(const ulonglong2*)&s->e[buf][3][eofs];
            }
            const float4 wA = *(const float4*)(wcI + (2 * g2 + 0) * 512);
            const float4 wB = *(const float4*)(wcI + (2 * g2 + 1) * 512);
            kp2(A, wA, cur.v0.x, cur.v1.x, cur.v2.x, cur.v3.x);
            kp2(A, wB, cur.v0.y, cur.v1.y, cur.v2.y, cur.v3.y);
            cur = nxt;
        }

        // Publish pre-activations: gate value = lane.x + lane.y.
        {
            const float2 r00 = u2f(A.a00), r01 = u2f(A.a01), r02 = u2f(A.a02), r03 = u2f(A.a03);
            const float2 r10 = u2f(A.a10), r11 = u2f(A.a11), r12 = u2f(A.a12), r13 = u2f(A.a13);
            s->gbuf[gp][0][j] = make_float2(r00.x + r00.y, r10.x + r10.y);
            s->gbuf[gp][1][j] = make_float2(r01.x + r01.y, r11.x + r11.y);
            s->gbuf[gp][2][j] = make_float2(r02.x + r02.y, r12.x + r12.y);
            s->gbuf[gp][3][j] = make_float2(r03.x + r03.y, r13.x + r13.y);
        }
        __syncthreads();

        // Gate combine: 512 cells over 256 threads, 2 each.
        #pragma unroll
        for (int r = 0; r < 2; r++) {
            const int idx = tid + r * 256;
            const int bc = idx >> 7, jj = idx & 127;
            const float2 gif = s->gbuf[0][bc][jj];   // (i, f)
            const float2 ggo = s->gbuf[1][bc][jj];   // (g, o)
            const float iv = sigf(gif.x);
            const float fv = sigf(gif.y);
            const float gv = tanf_(ggo.x);
            const float ov = sigf(ggo.y);
            const float cv = fv * s->c[bc][jj] + iv * gv;
            s->c[bc][jj] = cv;
            s->h[bc][jj] = ov * tanf_(cv);
        }
        if (doE) s->e[buf ^ 1][bcp][eep] = ev;
        tv = tvn;
        __syncthreads();
    }

    // Export final hidden state.
    for (int i = tid; i < BC * Hsz; i += 256)
        g_hfin[(b0 + (i >> 7)) * Hsz + (i & 127)] = s->h[i >> 7][i & 127];
}

// ---------------------------------------------------------------------------
// FC epilogue: out[b][n] = h_fin[b] . w_fc[n] + b_fc[n]
// ---------------------------------------------------------------------------
__global__ void fc_kernel(const float* __restrict__ b_fc, float* __restrict__ out) {
    __shared__ float hs[8][Hsz];
    const int tid = threadIdx.x;
    const int n   = blockIdx.x * 128 + tid;
    const int bb  = blockIdx.y * 8;
    for (int i = tid; i < 8 * Hsz; i += 128)
        hs[i >> 7][i & 127] = g_hfin[(bb + (i >> 7)) * Hsz + (i & 127)];
    __syncthreads();
    if (n >= NCLS) return;
    const float bv = b_fc[n];
    float acc[8];
    #pragma unroll
    for (int i = 0; i < 8; i++) acc[i] = bv;
    #pragma unroll 4
    for (int k = 0; k < Hsz; k++) {
        const float w = g_wfcT[k * NCLS + n];
        #pragma unroll
        for (int i = 0; i < 8; i++) acc[i] = fmaf(hs[i][k], w, acc[i]);
    }
    #pragma unroll
    for (int i = 0; i < 8; i++) out[(bb + i) * NCLS + n] = acc[i];
}

extern "C" void kernel_launch(void* const* d_in, const int* in_sizes, int n_in,
                              void* d_out, int out_size) {
    const int*   x    = (const int*)  d_in[0];
    const float* emb  = (const float*)d_in[1];
    const float* w_ih = (const float*)d_in[2];
    const float* w_hh = (const float*)d_in[3];
    const float* b_ih = (const float*)d_in[4];
    const float* b_hh = (const float*)d_in[5];
    const float* w_fc = (const float*)d_in[6];
    const float* b_fc = (const float*)d_in[7];
    float* out = (float*)d_out;

    static bool attr_set = false;
    if (!attr_set) {
        cudaFuncSetAttribute(lstm_kernel, cudaFuncAttributeMaxDynamicSharedMemorySize,
                             (int)sizeof(Smem));
        attr_set = true;
    }

    prep_kernel<<<1000, 256>>>(w_ih, w_hh, b_ih, b_hh, w_fc);
    lstm_kernel<<<Bsz / BC, 256, sizeof(Smem)>>>(x, emb);
    fc_kernel<<<dim3((NCLS + 127) / 128, Bsz / 8), 128>>>(b_fc, out);
}

// round 9
// speedup vs baseline: 1.3408x; 1.0548x over previous
#include <cuda_runtime.h>
#include <cuda_bf16.h>

#define Bsz  512
#define Ssz  1024
#define Esz  48
#define Hsz  128
#define NCLS 2000
#define BC   4              // batch rows per CTA
#define NKP  64             // total k-pairs
#define SPK  20             // k-pairs held in smem   (kp 0..19)
#define RPK  44             // k-pairs held in REGISTERS (kp 20..63)
#define EP   24             // e-pairs (all in smem)

// Packed parameter storage (prepared once per launch by prep_kernel).
// g_wKpack: [gp][kp][j][q]  q = (gate_lo_k, gate_lo_k+1, gate_hi_k, gate_hi_k+1)
// g_wIK   : [gp][ep][j][q]
// g_bias  : [gp][j][gi]     (= b_ih + b_hh)
__device__ float g_wKpack[2 * NKP * Hsz * 4];
__device__ float g_wIK   [2 * EP  * Hsz * 4];
__device__ float g_bias  [2 * Hsz * 2];
__device__ float g_wfcT  [Hsz * NCLS];
__device__ float g_hfin  [Bsz * Hsz];

typedef unsigned long long ull;

__device__ __forceinline__ void ffma2(ull& acc, ull a, ull b) {
    asm("fma.rn.f32x2 %0, %1, %2, %0;" : "+l"(acc) : "l"(a), "l"(b));
}
__device__ __forceinline__ ull f2u2(float x, float y) {
    ull r; asm("mov.b64 %0, {%1, %2};" : "=l"(r) : "f"(x), "f"(y)); return r;
}
__device__ __forceinline__ float2 u2f(ull v) {
    float2 r; asm("mov.b64 {%0, %1}, %2;" : "=f"(r.x), "=f"(r.y) : "l"(v)); return r;
}
__device__ __forceinline__ float tanha(float x) {
    float y; asm("tanh.approx.f32 %0, %1;" : "=f"(y) : "f"(x)); return y;
}
__device__ __forceinline__ float siga(float x) {
    return fmaf(0.5f, tanha(0.5f * x), 0.5f);
}

// ---------------------------------------------------------------------------
__global__ void prep_kernel(const float* __restrict__ w_ih, const float* __restrict__ w_hh,
                            const float* __restrict__ b_ih, const float* __restrict__ b_hh,
                            const float* __restrict__ w_fc) {
    int i = blockIdx.x * blockDim.x + threadIdx.x;
    if (i < 2 * NKP * Hsz * 4) {
        int q = i & 3, j = (i >> 2) & 127, kp = (i >> 9) & 63, gp = (i >> 15) & 1;
        int gate = gp * 2 + (q >> 1);
        int k = kp * 2 + (q & 1);
        g_wKpack[i] = w_hh[(gate * Hsz + j) * Hsz + k];
    }
    if (i < 2 * EP * Hsz * 4) {
        int q = i & 3, j = (i >> 2) & 127;
        int rest = i >> 9;                 // [0, 48)
        int ep = rest % EP, gp = rest / EP;
        int gate = gp * 2 + (q >> 1);
        int e = ep * 2 + (q & 1);
        g_wIK[i] = w_ih[(gate * Hsz + j) * Esz + e];
    }
    if (i < 2 * Hsz * 2) {
        int gi = i & 1, j = (i >> 1) & 127, gp = i >> 8;
        int r = (gp * 2 + gi) * Hsz + j;
        g_bias[i] = b_ih[r] + b_hh[r];
    }
    if (i < Hsz * NCLS) {
        int k = i / NCLS, n = i % NCLS;
        g_wfcT[i] = w_fc[n * Hsz + k];
    }
}

// ---------------------------------------------------------------------------
// LSTM recurrence, persistent-RNN: 176 weight registers per thread.
// Thread (gp, j): gates (2gp, 2gp+1) x 4 batches, f32x2 packed along k.
// Step structure: A arrives carrying bias + input-part(st); the k-GEMV adds
// the recurrent part; after bar1 the NEXT step's input-part is computed in
// the shadow of the MUFU-bound gate combine.
// ---------------------------------------------------------------------------
struct alignas(16) Smem {
    float  wih[2 * EP  * Hsz * 4];   //  96 KB (all e-pairs)
    float  whh[2 * SPK * Hsz * 4];   //  80 KB (k-pairs 0..SPK-1)
    float  h[BC][Hsz];               //   2 KB
    float2 gbuf[2][BC][Hsz];         //   8 KB  [gp][bc][j] = (g_2gp, g_2gp+1)
    float  e[2][BC][Esz];            // 1.5 KB  double-buffered embeddings
};

struct Acc8 {
    ull a00, a01, a02, a03, a10, a11, a12, a13;
};

__device__ __forceinline__ void kp2(Acc8& A, float4 w, ull o0, ull o1, ull o2, ull o3) {
    const ull pA = f2u2(w.x, w.y);
    const ull pB = f2u2(w.z, w.w);
    ffma2(A.a00, pA, o0); ffma2(A.a01, pA, o1);
    ffma2(A.a02, pA, o2); ffma2(A.a03, pA, o3);
    ffma2(A.a10, pB, o0); ffma2(A.a11, pB, o1);
    ffma2(A.a12, pB, o2); ffma2(A.a13, pB, o3);
}

__global__ void __launch_bounds__(256, 1)
lstm_kernel(const int* __restrict__ x, const float* __restrict__ emb) {
    extern __shared__ char smem_raw[];
    Smem* s = reinterpret_cast<Smem*>(smem_raw);

    const int tid = threadIdx.x;
    const int j   = tid & 127;
    const int gp  = tid >> 7;
    const int b0  = blockIdx.x * BC;

    // Stage smem-resident weights.
    for (int i = tid; i < 2 * EP * Hsz * 4; i += 256) s->wih[i] = g_wIK[i];
    for (int g = 0; g < 2; g++)
        for (int i = tid; i < SPK * Hsz * 4; i += 256)
            s->whh[g * (SPK * 512) + i] = g_wKpack[g * (NKP * 512) + i];
    for (int i = tid; i < BC * Hsz; i += 256)
        s->h[i >> 7][i & 127] = 0.0f;

    // Load this thread's REGISTER-RESIDENT weights: k-pairs SPK..NKP-1.
    float4 wreg[RPK];
    {
        const float4* __restrict__ src =
            (const float4*)(g_wKpack + (gp * NKP + SPK) * 512 + j * 4);
        #pragma unroll
        for (int r = 0; r < RPK; r++)
            wreg[r] = src[r * 128];          // stride 512 floats = 128 float4
    }

    // Embedding prefetch lanes: 192 threads, one (bc, e) element each.
    const int  bcp = tid / Esz;
    const int  eep = tid - bcp * Esz;
    const bool eTh = (tid < BC * Esz);
    int tv = 0;
    if (eTh) {
        const int t0 = __ldg(&x[(b0 + bcp) * Ssz + 0]);
        s->e[0][bcp][eep] = __ldg(&emb[t0 * Esz + eep]);   // e(0) -> buf 0
        tv = __ldg(&x[(b0 + bcp) * Ssz + 1]);
    }

    const float2 b2 = *(const float2*)(g_bias + (gp * Hsz + j) * 2);
    const ull bias0 = f2u2(b2.x, 0.0f);
    const ull bias1 = f2u2(b2.y, 0.0f);
    const float* __restrict__ wcH = s->whh + gp * (SPK * 512) + j * 4;
    const float* __restrict__ wcI = s->wih + gp * (EP  * 512) + j * 4;

    // Cell state in registers: this thread permanently owns cells
    // (bc0,jj0)=(tid>>7, tid&127) and (bc1,jj1)=+256.
    float c0 = 0.0f, c1 = 0.0f;
    const int bcA = tid >> 7,        jjA = tid & 127;
    const int bcB = (tid + 256) >> 7, jjB = tid & 127;
    __syncthreads();

    // Prologue: A = bias + input-part(e(0)).
    Acc8 A;
    A.a00 = bias0; A.a01 = bias0; A.a02 = bias0; A.a03 = bias0;
    A.a10 = bias1; A.a11 = bias1; A.a12 = bias1; A.a13 = bias1;
    #pragma unroll
    for (int g2 = 0; g2 < EP / 2; g2++) {
        const ulonglong2 e0 = *(const ulonglong2*)&s->e[0][0][g2 * 4];
        const ulonglong2 e1 = *(const ulonglong2*)&s->e[0][1][g2 * 4];
        const ulonglong2 e2 = *(const ulonglong2*)&s->e[0][2][g2 * 4];
        const ulonglong2 e3 = *(const ulonglong2*)&s->e[0][3][g2 * 4];
        const float4 wA = *(const float4*)(wcI + (2 * g2 + 0) * 512);
        const float4 wB = *(const float4*)(wcI + (2 * g2 + 1) * 512);
        kp2(A, wA, e0.x, e1.x, e2.x, e3.x);
        kp2(A, wB, e0.y, e1.y, e2.y, e3.y);
    }

    for (int st = 0; st < Ssz; st++) {
        const int nbuf = (st + 1) & 1;

        // Prefetch embedding row for step st+1 + token for st+2.
        float ev = 0.0f;
        const bool doE = eTh && (st + 1 < Ssz);
        if (doE) ev = __ldg(&emb[tv * Esz + eep]);
        int tvn = 0;
        if (eTh && (st + 2 < Ssz)) tvn = __ldg(&x[(b0 + bcp) * Ssz + st + 2]);

        // --- recurrent GEMV, REGISTER k-pairs [SPK, NKP) ---
        #pragma unroll
        for (int r2 = 0; r2 < RPK / 2; r2++) {
            const int hofs = 2 * SPK + r2 * 4;
            const ulonglong2 h0 = *(const ulonglong2*)&s->h[0][hofs];
            const ulonglong2 h1 = *(const ulonglong2*)&s->h[1][hofs];
            const ulonglong2 h2 = *(const ulonglong2*)&s->h[2][hofs];
            const ulonglong2 h3 = *(const ulonglong2*)&s->h[3][hofs];
            kp2(A, wreg[2 * r2 + 0], h0.x, h1.x, h2.x, h3.x);
            kp2(A, wreg[2 * r2 + 1], h0.y, h1.y, h2.y, h3.y);
        }
        // --- recurrent GEMV, smem k-pairs [0, SPK) ---
        #pragma unroll
        for (int g2 = 0; g2 < SPK / 2; g2++) {
            const ulonglong2 h0 = *(const ulonglong2*)&s->h[0][g2 * 4];
            const ulonglong2 h1 = *(const ulonglong2*)&s->h[1][g2 * 4];
            const ulonglong2 h2 = *(const ulonglong2*)&s->h[2][g2 * 4];
            const ulonglong2 h3 = *(const ulonglong2*)&s->h[3][g2 * 4];
            const float4 wA = *(const float4*)(wcH + (2 * g2 + 0) * 512);
            const float4 wB = *(const float4*)(wcH + (2 * g2 + 1) * 512);
            kp2(A, wA, h0.x, h1.x, h2.x, h3.x);
            kp2(A, wB, h0.y, h1.y, h2.y, h3.y);
        }

        // Publish pre-activations (gate value = lane.x + lane.y) and next e.
        {
            const float2 r00 = u2f(A.a00), r01 = u2f(A.a01), r02 = u2f(A.a02), r03 = u2f(A.a03);
            const float2 r10 = u2f(A.a10), r11 = u2f(A.a11), r12 = u2f(A.a12), r13 = u2f(A.a13);
            s->gbuf[gp][0][j] = make_float2(r00.x + r00.y, r10.x + r10.y);
            s->gbuf[gp][1][j] = make_float2(r01.x + r01.y, r11.x + r11.y);
            s->gbuf[gp][2][j] = make_float2(r02.x + r02.y, r12.x + r12.y);
            s->gbuf[gp][3][j] = make_float2(r03.x + r03.y, r13.x + r13.y);
        }
        if (doE) s->e[nbuf][bcp][eep] = ev;
        tv = tvn;
        __syncthreads();

        // --- combine (MUFU-bound) + input-part(st+1) (fma-bound) overlap ---
        const float2 gifA = s->gbuf[0][bcA][jjA];
        const float2 ggoA = s->gbuf[1][bcA][jjA];
        const float2 gifB = s->gbuf[0][bcB][jjB];
        const float2 ggoB = s->gbuf[1][bcB][jjB];

        A.a00 = bias0; A.a01 = bias0; A.a02 = bias0; A.a03 = bias0;
        A.a10 = bias1; A.a11 = bias1; A.a12 = bias1; A.a13 = bias1;
        #pragma unroll
        for (int g2 = 0; g2 < EP / 2; g2++) {
            const ulonglong2 e0 = *(const ulonglong2*)&s->e[nbuf][0][g2 * 4];
            const ulonglong2 e1 = *(const ulonglong2*)&s->e[nbuf][1][g2 * 4];
            const ulonglong2 e2 = *(const ulonglong2*)&s->e[nbuf][2][g2 * 4];
            const ulonglong2 e3 = *(const ulonglong2*)&s->e[nbuf][3][g2 * 4];
            const float4 wA = *(const float4*)(wcI + (2 * g2 + 0) * 512);
            const float4 wB = *(const float4*)(wcI + (2 * g2 + 1) * 512);
            kp2(A, wA, e0.x, e1.x, e2.x, e3.x);
            kp2(A, wB, e0.y, e1.y, e2.y, e3.y);
        }
        {
            const float ivA = siga(gifA.x), fvA = siga(gifA.y);
            const float gvA = tanha(ggoA.x), ovA = siga(ggoA.y);
            c0 = fvA * c0 + ivA * gvA;
            s->h[bcA][jjA] = ovA * tanha(c0);
            const float ivB = siga(gifB.x), fvB = siga(gifB.y);
            const float gvB = tanha(ggoB.x), ovB = siga(ggoB.y);
            c1 = fvB * c1 + ivB * gvB;
            s->h[bcB][jjB] = ovB * tanha(c1);
        }
        __syncthreads();
    }

    // Export final hidden state.
    for (int i = tid; i < BC * Hsz; i += 256)
        g_hfin[(b0 + (i >> 7)) * Hsz + (i & 127)] = s->h[i >> 7][i & 127];
}

// ---------------------------------------------------------------------------
// FC epilogue: out[b][n] = h_fin[b] . w_fc[n] + b_fc[n]
// ---------------------------------------------------------------------------
__global__ void fc_kernel(const float* __restrict__ b_fc, float* __restrict__ out) {
    __shared__ float hs[8][Hsz];
    const int tid = threadIdx.x;
    const int n   = blockIdx.x * 128 + tid;
    const int bb  = blockIdx.y * 8;
    for (int i = tid; i < 8 * Hsz; i += 128)
        hs[i >> 7][i & 127] = g_hfin[(bb + (i >> 7)) * Hsz + (i & 127)];
    __syncthreads();
    if (n >= NCLS) return;
    const float bv = b_fc[n];
    float acc[8];
    #pragma unroll
    for (int i = 0; i < 8; i++) acc[i] = bv;
    #pragma unroll 4
    for (int k = 0; k < Hsz; k++) {
        const float w = g_wfcT[k * NCLS + n];
        #pragma unroll
        for (int i = 0; i < 8; i++) acc[i] = fmaf(hs[i][k], w, acc[i]);
    }
    #pragma unroll
    for (int i = 0; i < 8; i++) out[(bb + i) * NCLS + n] = acc[i];
}

extern "C" void kernel_launch(void* const* d_in, const int* in_sizes, int n_in,
                              void* d_out, int out_size) {
    const int*   x    = (const int*)  d_in[0];
    const float* emb  = (const float*)d_in[1];
    const float* w_ih = (const float*)d_in[2];
    const float* w_hh = (const float*)d_in[3];
    const float* b_ih = (const float*)d_in[4];
    const float* b_hh = (const float*)d_in[5];
    const float* w_fc = (const float*)d_in[6];
    const float* b_fc = (const float*)d_in[7];
    float* out = (float*)d_out;

    static bool attr_set = false;
    if (!attr_set) {
        cudaFuncSetAttribute(lstm_kernel, cudaFuncAttributeMaxDynamicSharedMemorySize,
                             (int)sizeof(Smem));
        attr_set = true;
    }

    prep_kernel<<<1000, 256>>>(w_ih, w_hh, b_ih, b_hh, w_fc);
    lstm_kernel<<<Bsz / BC, 256, sizeof(Smem)>>>(x, emb);
    fc_kernel<<<dim3((NCLS + 127) / 128, Bsz / 8), 128>>>(b_fc, out);
}

// round 11
// speedup vs baseline: 2.0278x; 1.5124x over previous
#include <cuda_runtime.h>
#include <cuda_bf16.h>
#include <cstdint>

#define Bsz  512
#define Ssz  1024
#define Esz  48
#define Hsz  128
#define NCLS 2000
#define NB   8                 // batches per CTA (MMA n dim)
#define NCTA (Bsz / NB)        // 64
#define NKK  11                // K chunks of 16 (176 = 128 h + 48 e)
#define NFR  (32 * NKK)        // 352 A-fragments per CTA (32 m-tiles x 11 k)
#define FRW  44                // fragments per warp (4 m-tiles x 11 k)
#define SROW 90                // state row stride in u32 (88 used + pad)
#define GST  12                // gbufT row stride in floats

// Prepared parameters (built by prep_kernel each launch).
// g_whiFrag/g_wloFrag: u32[NFR*128], fragment-shuffled bf16x2 weight images.
//   u32 index = fragblk*128 + lane*4 + ri ; fragblk = w*44 + kk*4 + mt.
__device__ uint32_t g_whiFrag[NFR * 128];
__device__ uint32_t g_wloFrag[NFR * 128];
__device__ float    g_bias4[4 * Hsz];
__device__ float    g_wfcT[Hsz * NCLS];
__device__ float    g_hfin[Bsz * Hsz];

__device__ __forceinline__ float tanha(float x) {
    float y; asm("tanh.approx.f32 %0, %1;" : "=f"(y) : "f"(x)); return y;
}
__device__ __forceinline__ float siga(float x) { return fmaf(0.5f, tanha(0.5f * x), 0.5f); }

// m16n8k16 bf16 MMA, fp32 accumulate (HMMA; baseline PTX, sm_80+).
__device__ __forceinline__ void mma(float* d, uint4 a, uint32_t b0, uint32_t b1) {
    asm volatile("mma.sync.aligned.m16n8k16.row.col.f32.bf16.bf16.f32 "
        "{%0,%1,%2,%3}, {%4,%5,%6,%7}, {%8,%9}, {%0,%1,%2,%3};"
        : "+f"(d[0]), "+f"(d[1]), "+f"(d[2]), "+f"(d[3])
        : "r"(a.x), "r"(a.y), "r"(a.z), "r"(a.w), "r"(b0), "r"(b1));
}

// ---------------------------------------------------------------------------
// Prep: build fragment-shuffled hi/lo weight images, bias, fc transpose.
// Weight matrix W[512,176]: rows gate-major (i,f,g,o x 128 j, PyTorch order);
// cols K: 0..127 = w_hh, 128..175 = w_ih.
// A-frag layout (m16n8k16 row-major A): lane l, regs a0..a3:
//   a0 (r, c0|c0+1)  a1 (r+8, ..)  a2 (r, c0+8|+9)  a3 (r+8, c0+8|+9)
//   r = l>>2, c0 = (l&3)*2 ; R = w*64 + mt*16 + r ; K = kk*16 + c.
// ---------------------------------------------------------------------------
__global__ void prep_kernel(const float* __restrict__ w_ih, const float* __restrict__ w_hh,
                            const float* __restrict__ b_ih, const float* __restrict__ b_hh,
                            const float* __restrict__ w_fc) {
    int i = blockIdx.x * blockDim.x + threadIdx.x;
    if (i < NFR * 128) {
        int fragblk = i >> 7, rem = i & 127;
        int lane = rem >> 2, ri = rem & 3;
        int w = fragblk / FRW, f = fragblk % FRW, kk = f >> 2, mt = f & 3;
        int r  = (lane >> 2) + (ri & 1) * 8;
        int c0 = (lane & 3) * 2 + (ri >> 1) * 8;
        int R = w * 64 + mt * 16 + r;
        int K = kk * 16 + c0;
        float v0 = (K     < 128) ? w_hh[R * Hsz + K]     : w_ih[R * Esz + K - 128];
        float v1 = (K + 1 < 128) ? w_hh[R * Hsz + K + 1] : w_ih[R * Esz + K + 1 - 128];
        __nv_bfloat16 h0 = __float2bfloat16(v0), h1 = __float2bfloat16(v1);
        __nv_bfloat16 l0 = __float2bfloat16(v0 - __bfloat162float(h0));
        __nv_bfloat16 l1 = __float2bfloat16(v1 - __bfloat162float(h1));
        g_whiFrag[i] = (uint32_t)__bfloat16_as_ushort(h0) | ((uint32_t)__bfloat16_as_ushort(h1) << 16);
        g_wloFrag[i] = (uint32_t)__bfloat16_as_ushort(l0) | ((uint32_t)__bfloat16_as_ushort(l1) << 16);
    }
    if (i < 4 * Hsz) g_bias4[i] = b_ih[i] + b_hh[i];
    if (i < Hsz * NCLS) {
        int k = i / NCLS, n = i % NCLS;
        g_wfcT[i] = w_fc[n * Hsz + k];
    }
}

// ---------------------------------------------------------------------------
// LSTM recurrence: HMMA per-step batched GEMM, 8 batches per CTA, 64 CTAs.
// D = Whi*s_hi + Whi*s_lo + Wlo*s_hi   (3-term bf16, fp32 accumulate)
// state smem: sHi/sLo u32[b][kpair] (bf16x2, kpair = k/2), SROW stride.
// ---------------------------------------------------------------------------
struct alignas(16) Smem {
    uint32_t whiA[NFR * 128];      // 176 KB fragment image of Whi
    uint32_t sHi[NB * SROW];       // 2.8 KB state hi
    uint32_t sLo[NB * SROW];       // 2.8 KB state lo
    float    gbufT[4 * Hsz * GST]; // 24 KB gates [g][j][b], stride 12
};

__device__ __forceinline__ void write_state(Smem* s, int b, int k, float v) {
    __nv_bfloat16 hi = __float2bfloat16(v);
    __nv_bfloat16 lo = __float2bfloat16(v - __bfloat162float(hi));
    const int kp = k >> 1, hf = k & 1;
    ((uint16_t*)&s->sHi[b * SROW + kp])[hf] = __bfloat16_as_ushort(hi);
    ((uint16_t*)&s->sLo[b * SROW + kp])[hf] = __bfloat16_as_ushort(lo);
}

__global__ void __launch_bounds__(256, 1)
lstm_kernel(const int* __restrict__ x, const float* __restrict__ emb) {
    extern __shared__ char smraw[];
    Smem* s = (Smem*)smraw;
    const int tid = threadIdx.x;
    const int w   = tid >> 5, l = tid & 31;
    const int B0  = blockIdx.x * NB;

    // Stage Whi fragments into smem; zero state.
    for (int i = tid; i < NFR * 128 / 4; i += 256)
        ((uint4*)s->whiA)[i] = ((const uint4*)g_whiFrag)[i];
    for (int i = tid; i < NB * SROW; i += 256) { s->sHi[i] = 0; s->sLo[i] = 0; }

    // Wlo fragments: stationary in registers (44 uint4 = 176 regs).
    uint4 wlo[FRW];
    #pragma unroll
    for (int f = 0; f < FRW; f++)
        wlo[f] = ((const uint4*)g_wloFrag)[(w * FRW + f) * 32 + l];

    // Embedding slots: slot s -> (b = s/48, e = s%48); 384 slots over 256 thr.
    const int  sb0 = tid / Esz, se0 = tid % Esz;
    const bool has1 = (tid < 128);
    const int  sb1 = (tid + 256) / Esz, se1 = (tid + 256) % Esz;
    int tv0 = 0, tv1 = 0;
    __syncthreads();     // state zero visible before e(0) writes
    {
        const int t0 = __ldg(&x[(B0 + sb0) * Ssz]);
        write_state(s, sb0, 128 + se0, __ldg(&emb[t0 * Esz + se0]));
        tv0 = __ldg(&x[(B0 + sb0) * Ssz + 1]);
        if (has1) {
            const int t1 = __ldg(&x[(B0 + sb1) * Ssz]);
            write_state(s, sb1, 128 + se1, __ldg(&emb[t1 * Esz + se1]));
            tv1 = __ldg(&x[(B0 + sb1) * Ssz + 1]);
        }
    }

    // Combine-phase cell ownership: thread -> (j, batches bq..bq+3).
    const int j  = tid & 127;
    const int bq = (tid >> 7) * 4;
    const float bI = g_bias4[j],          bF = g_bias4[128 + j];
    const float bG = g_bias4[256 + j],    bO = g_bias4[384 + j];
    float c4[4] = {0, 0, 0, 0}, h4[4] = {0, 0, 0, 0};

    // B-frag pointers: lane l covers n = l>>2, kpair base = l&3.
    const uint32_t* shiP = s->sHi + (l >> 2) * SROW + (l & 3);
    const uint32_t* sloP = s->sLo + (l >> 2) * SROW + (l & 3);
    const uint4* aP = (const uint4*)(s->whiA) + w * FRW * 32 + l;
    float* gb = s->gbufT;
    const int g  = w >> 1;           // this warp's gate
    const int jb = (w & 1) * 64;     // j base within gate
    __syncthreads();

    for (int st = 0; st < Ssz; st++) {
        // Prefetch next step's embeddings + tokens (fly under HMMA).
        const bool doE = (st + 1 < Ssz);
        float ev0 = 0.0f, ev1 = 0.0f; int tn0 = 0, tn1 = 0;
        if (doE) {
            ev0 = __ldg(&emb[tv0 * Esz + se0]);
            if (has1) ev1 = __ldg(&emb[tv1 * Esz + se1]);
        }
        if (st + 2 < Ssz) {
            tn0 = __ldg(&x[(B0 + sb0) * Ssz + st + 2]);
            if (has1) tn1 = __ldg(&x[(B0 + sb1) * Ssz + st + 2]);
        }

        // --- HMMA phase: 4 m-tiles x 11 k-chunks x 3 terms ---
        float d[16];
        #pragma unroll
        for (int q = 0; q < 16; q++) d[q] = 0.0f;
        #pragma unroll
        for (int kk = 0; kk < NKK; kk++) {
            const uint32_t bhi0 = shiP[kk * 8], bhi1 = shiP[kk * 8 + 4];
            const uint32_t blo0 = sloP[kk * 8], blo1 = sloP[kk * 8 + 4];
            #pragma unroll
            for (int mt = 0; mt < 4; mt++) {
                const uint4 ahi = aP[(kk * 4 + mt) * 32];
                mma(&d[mt * 4], ahi, bhi0, bhi1);             // Whi * s_hi
                mma(&d[mt * 4], ahi, blo0, blo1);             // Whi * s_lo
                mma(&d[mt * 4], wlo[kk * 4 + mt], bhi0, bhi1);// Wlo * s_hi
            }
        }

        // Publish D to gbufT[g][j][b] (stride 12).
        #pragma unroll
        for (int mt = 0; mt < 4; mt++) {
            const int jj = jb + mt * 16 + (l >> 2);
            const int bb = (l & 3) * 2;
            float* p0 = gb + g * (Hsz * GST) + jj * GST + bb;
            p0[0] = d[mt * 4 + 0]; p0[1] = d[mt * 4 + 1];
            float* p1 = p0 + 8 * GST;
            p1[0] = d[mt * 4 + 2]; p1[1] = d[mt * 4 + 3];
        }
        __syncthreads();

        // --- combine: 4 cells (j, bq..bq+3) per thread ---
        const float4 gI = *(const float4*)(gb + 0 * (Hsz * GST) + j * GST + bq);
        const float4 gF = *(const float4*)(gb + 1 * (Hsz * GST) + j * GST + bq);
        const float4 gG = *(const float4*)(gb + 2 * (Hsz * GST) + j * GST + bq);
        const float4 gO = *(const float4*)(gb + 3 * (Hsz * GST) + j * GST + bq);
        #pragma unroll
        for (int q = 0; q < 4; q++) {
            const float iv = siga(((const float*)&gI)[q] + bI);
            const float fv = siga(((const float*)&gF)[q] + bF);
            const float gv = tanha(((const float*)&gG)[q] + bG);
            const float ov = siga(((const float*)&gO)[q] + bO);
            c4[q] = fv * c4[q] + iv * gv;
            const float hv = ov * tanha(c4[q]);
            h4[q] = hv;
            write_state(s, bq + q, j, hv);
        }
        if (doE) {
            write_state(s, sb0, 128 + se0, ev0);
            if (has1) write_state(s, sb1, 128 + se1, ev1);
        }
        tv0 = tn0; tv1 = tn1;
        __syncthreads();
    }

    // Export final hidden state.
    #pragma unroll
    for (int q = 0; q < 4; q++)
        g_hfin[(B0 + bq + q) * Hsz + j] = h4[q];
}

// ---------------------------------------------------------------------------
// FC epilogue: out[b][n] = h_fin[b] . w_fc[n] + b_fc[n]
// ---------------------------------------------------------------------------
__global__ void fc_kernel(const float* __restrict__ b_fc, float* __restrict__ out) {
    __shared__ float hs[8][Hsz];
    const int tid = threadIdx.x;
    const int n   = blockIdx.x * 128 + tid;
    const int bb  = blockIdx.y * 8;
    for (int i = tid; i < 8 * Hsz; i += 128)
        hs[i >> 7][i & 127] = g_hfin[(bb + (i >> 7)) * Hsz + (i & 127)];
    __syncthreads();
    if (n >= NCLS) return;
    const float bv = b_fc[n];
    float acc[8];
    #pragma unroll
    for (int i = 0; i < 8; i++) acc[i] = bv;
    #pragma unroll 4
    for (int k = 0; k < Hsz; k++) {
        const float w = g_wfcT[k * NCLS + n];
        #pragma unroll
        for (int i = 0; i < 8; i++) acc[i] = fmaf(hs[i][k], w, acc[i]);
    }
    #pragma unroll
    for (int i = 0; i < 8; i++) out[(bb + i) * NCLS + n] = acc[i];
}

extern "C" void kernel_launch(void* const* d_in, const int* in_sizes, int n_in,
                              void* d_out, int out_size) {
    const int*   x    = (const int*)  d_in[0];
    const float* emb  = (const float*)d_in[1];
    const float* w_ih = (const float*)d_in[2];
    const float* w_hh = (const float*)d_in[3];
    const float* b_ih = (const float*)d_in[4];
    const float* b_hh = (const float*)d_in[5];
    const float* w_fc = (const float*)d_in[6];
    const float* b_fc = (const float*)d_in[7];
    float* out = (float*)d_out;

    static bool attr_set = false;
    if (!attr_set) {
        cudaFuncSetAttribute(lstm_kernel, cudaFuncAttributeMaxDynamicSharedMemorySize,
                             (int)sizeof(Smem));
        attr_set = true;
    }

    prep_kernel<<<1000, 256>>>(w_ih, w_hh, b_ih, b_hh, w_fc);
    lstm_kernel<<<NCTA, 256, sizeof(Smem)>>>(x, emb);
    fc_kernel<<<dim3((NCLS + 127) / 128, Bsz / 8), 128>>>(b_fc, out);
}

// round 12
// speedup vs baseline: 2.1509x; 1.0607x over previous
#include <cuda_runtime.h>
#include <cuda_bf16.h>
#include <cstdint>

#define Bsz  512
#define Ssz  1024
#define Esz  48
#define Hsz  128
#define NCLS 2000
#define NB   8                 // batches per CTA (MMA n dim)
#define NCTA (Bsz / NB)        // 64
#define NKK  11                // K chunks of 16 (176 = 128 h + 48 e)
#define NFR  (32 * NKK)        // 352 A-fragments per CTA
#define FRW  44                // fragments per warp (11 k x 4 gates)
#define SROW 90                // state row stride in u32 (88 used + pad)

// Prepared parameters (built by prep_kernel each launch).
// Fragment images: u32 index = fragblk*128 + lane*4 + ri,
//   fragblk = w*44 + kk*4 + g  ->  W rows g*128 + w*16 + r  (warp = j-slice!)
__device__ uint32_t g_whiFrag[NFR * 128];
__device__ uint32_t g_wloFrag[NFR * 128];
__device__ float    g_bias4[4 * Hsz];
__device__ float    g_wfcT[Hsz * NCLS];
__device__ float    g_hfin[Bsz * Hsz];

__device__ __forceinline__ float tanha(float x) {
    float y; asm("tanh.approx.f32 %0, %1;" : "=f"(y) : "f"(x)); return y;
}
__device__ __forceinline__ float siga(float x) { return fmaf(0.5f, tanha(0.5f * x), 0.5f); }

// m16n8k16 bf16 MMA, fp32 accumulate (baseline PTX, sm_80+).
__device__ __forceinline__ void mma(float* d, uint4 a, uint32_t b0, uint32_t b1) {
    asm volatile("mma.sync.aligned.m16n8k16.row.col.f32.bf16.bf16.f32 "
        "{%0,%1,%2,%3}, {%4,%5,%6,%7}, {%8,%9}, {%0,%1,%2,%3};"
        : "+f"(d[0]), "+f"(d[1]), "+f"(d[2]), "+f"(d[3])
        : "r"(a.x), "r"(a.y), "r"(a.z), "r"(a.w), "r"(b0), "r"(b1));
}

// ---------------------------------------------------------------------------
// Prep. W[512,176]: rows gate-major (PyTorch i,f,g,o), K: 0..127 w_hh, 128..175 w_ih.
// A-frag (m16n8k16 row-A): lane l, reg ri: r=(l>>2)+(ri&1)*8, c0=(l&3)*2+(ri>>1)*8.
// Warp mapping: fragblk = w*44 + kk*4 + g  ->  R = g*128 + w*16 + r, K = kk*16+c.
// ---------------------------------------------------------------------------
__global__ void prep_kernel(const float* __restrict__ w_ih, const float* __restrict__ w_hh,
                            const float* __restrict__ b_ih, const float* __restrict__ b_hh,
                            const float* __restrict__ w_fc) {
    int i = blockIdx.x * blockDim.x + threadIdx.x;
    if (i < NFR * 128) {
        int fragblk = i >> 7, rem = i & 127;
        int lane = rem >> 2, ri = rem & 3;
        int w = fragblk / FRW, f = fragblk % FRW, kk = f >> 2, g = f & 3;
        int r  = (lane >> 2) + (ri & 1) * 8;
        int c0 = (lane & 3) * 2 + (ri >> 1) * 8;
        int R = g * 128 + w * 16 + r;
        int K = kk * 16 + c0;
        float v0 = (K     < 128) ? w_hh[R * Hsz + K]     : w_ih[R * Esz + K - 128];
        float v1 = (K + 1 < 128) ? w_hh[R * Hsz + K + 1] : w_ih[R * Esz + K + 1 - 128];
        __nv_bfloat16 h0 = __float2bfloat16(v0), h1 = __float2bfloat16(v1);
        __nv_bfloat16 l0 = __float2bfloat16(v0 - __bfloat162float(h0));
        __nv_bfloat16 l1 = __float2bfloat16(v1 - __bfloat162float(h1));
        g_whiFrag[i] = (uint32_t)__bfloat16_as_ushort(h0) | ((uint32_t)__bfloat16_as_ushort(h1) << 16);
        g_wloFrag[i] = (uint32_t)__bfloat16_as_ushort(l0) | ((uint32_t)__bfloat16_as_ushort(l1) << 16);
    }
    if (i < 4 * Hsz) g_bias4[i] = b_ih[i] + b_hh[i];
    if (i < Hsz * NCLS) {
        int k = i / NCLS, n = i % NCLS;
        g_wfcT[i] = w_fc[n * Hsz + k];
    }
}

// ---------------------------------------------------------------------------
// LSTM recurrence: fragment-aligned combine, double-buffered state,
// one barrier per step.  D = Whi*s_hi + Whi*s_lo + Wlo*s_hi  (fp32 acc).
// ---------------------------------------------------------------------------
struct alignas(16) Smem {
    uint32_t whiA[NFR * 128];      // 176 KB fragment image of Whi
    uint32_t sHi[2][NB * SROW];    // state hi, double-buffered
    uint32_t sLo[2][NB * SROW];    // state lo
};

__device__ __forceinline__ void write_state(uint32_t* hiB, uint32_t* loB,
                                            int b, int k, float v) {
    __nv_bfloat16 hi = __float2bfloat16(v);
    __nv_bfloat16 lo = __float2bfloat16(v - __bfloat162float(hi));
    const int kp = k >> 1, hf = k & 1;
    ((uint16_t*)&hiB[b * SROW + kp])[hf] = __bfloat16_as_ushort(hi);
    ((uint16_t*)&loB[b * SROW + kp])[hf] = __bfloat16_as_ushort(lo);
}

__global__ void __launch_bounds__(256, 1)
lstm_kernel(const int* __restrict__ x, const float* __restrict__ emb) {
    extern __shared__ char smraw[];
    Smem* s = (Smem*)smraw;
    const int tid = threadIdx.x;
    const int w   = tid >> 5, l = tid & 31;
    const int B0  = blockIdx.x * NB;

    // Stage Whi fragments; zero both state buffers.
    for (int i = tid; i < NFR * 128 / 4; i += 256)
        ((uint4*)s->whiA)[i] = ((const uint4*)g_whiFrag)[i];
    for (int i = tid; i < 2 * NB * SROW; i += 256) {
        (&s->sHi[0][0])[i] = 0;
        (&s->sLo[0][0])[i] = 0;
    }

    // Wlo fragments: stationary in registers (44 uint4 = 176 regs).
    uint4 wlo[FRW];
    #pragma unroll
    for (int f = 0; f < FRW; f++)
        wlo[f] = ((const uint4*)g_wloFrag)[(w * FRW + f) * 32 + l];

    // This lane's cells: j0/j1 = w*16 + (l>>2) [+8], b0/b1 = (l&3)*2 [+1].
    const int r0 = l >> 2;
    const int c0 = (l & 3) * 2;
    const int j0 = w * 16 + r0, j1 = j0 + 8;
    float bias_[4][2];
    #pragma unroll
    for (int g = 0; g < 4; g++) {
        bias_[g][0] = g_bias4[g * Hsz + j0];
        bias_[g][1] = g_bias4[g * Hsz + j1];
    }
    float cc[4] = {0, 0, 0, 0};   // cells q: (row r0,b0)(r0,b1)(r1,b0)(r1,b1)

    // Embedding slots: slot -> (b = slot/48, e = slot%48); 384 slots / 256 thr.
    const int  sb0 = tid / Esz, se0 = tid % Esz;
    const bool has1 = (tid < 128);
    const int  sb1 = (tid + 256) / Esz, se1 = (tid + 256) % Esz;
    int tv0 = 0, tv1 = 0;
    __syncthreads();     // zeros visible before e(0) writes
    {
        const int t0 = __ldg(&x[(B0 + sb0) * Ssz]);
        write_state(s->sHi[0], s->sLo[0], sb0, 128 + se0, __ldg(&emb[t0 * Esz + se0]));
        tv0 = __ldg(&x[(B0 + sb0) * Ssz + 1]);
        if (has1) {
            const int t1 = __ldg(&x[(B0 + sb1) * Ssz]);
            write_state(s->sHi[0], s->sLo[0], sb1, 128 + se1, __ldg(&emb[t1 * Esz + se1]));
            tv1 = __ldg(&x[(B0 + sb1) * Ssz + 1]);
        }
    }
    const uint4* aP = (const uint4*)(s->whiA) + w * FRW * 32 + l;
    __syncthreads();

    for (int st = 0; st < Ssz; st++) {
        const int buf = st & 1, nbuf = buf ^ 1;
        const uint32_t* sh = s->sHi[buf] + (l >> 2) * SROW + (l & 3);
        const uint32_t* sl = s->sLo[buf] + (l >> 2) * SROW + (l & 3);
        uint32_t* nHi = s->sHi[nbuf];
        uint32_t* nLo = s->sLo[nbuf];

        // Prefetch next embeddings/tokens (fly under HMMA).
        const bool doE = (st + 1 < Ssz);
        float ev0 = 0.0f, ev1 = 0.0f; int tn0 = 0, tn1 = 0;
        if (doE) {
            ev0 = __ldg(&emb[tv0 * Esz + se0]);
            if (has1) ev1 = __ldg(&emb[tv1 * Esz + se1]);
        }
        if (st + 2 < Ssz) {
            tn0 = __ldg(&x[(B0 + sb0) * Ssz + st + 2]);
            if (has1) tn1 = __ldg(&x[(B0 + sb1) * Ssz + st + 2]);
        }

        // Accumulators pre-seeded with bias (per gate / per row).
        float d[16];
        #pragma unroll
        for (int g = 0; g < 4; g++) {
            d[g * 4 + 0] = bias_[g][0]; d[g * 4 + 1] = bias_[g][0];
            d[g * 4 + 2] = bias_[g][1]; d[g * 4 + 3] = bias_[g][1];
        }

        // --- HMMA: 11 k-chunks x (3 terms x 4 gates), term-major interleave ---
        #pragma unroll
        for (int kk = 0; kk < NKK; kk++) {
            const uint32_t bhi0 = sh[kk * 8], bhi1 = sh[kk * 8 + 4];
            const uint32_t blo0 = sl[kk * 8], blo1 = sl[kk * 8 + 4];
            uint4 ahi[4];
            #pragma unroll
            for (int g = 0; g < 4; g++) ahi[g] = aP[(kk * 4 + g) * 32];
            #pragma unroll
            for (int g = 0; g < 4; g++) mma(&d[g * 4], ahi[g], bhi0, bhi1);
            #pragma unroll
            for (int g = 0; g < 4; g++) mma(&d[g * 4], ahi[g], blo0, blo1);
            #pragma unroll
            for (int g = 0; g < 4; g++) mma(&d[g * 4], wlo[kk * 4 + g], bhi0, bhi1);
        }

        // --- in-register combine: 4 cells, gates i/f/g/o = d[0/4/8/12 + q] ---
        #pragma unroll
        for (int q = 0; q < 4; q++) {
            const float iv = siga(d[0 + q]);
            const float fv = siga(d[4 + q]);
            const float gv = tanha(d[8 + q]);
            const float ov = siga(d[12 + q]);
            cc[q] = fv * cc[q] + iv * gv;
            const float hv = ov * tanha(cc[q]);
            write_state(nHi, nLo, c0 + (q & 1), j0 + (q >> 1) * 8, hv);
        }
        if (doE) {
            write_state(nHi, nLo, sb0, 128 + se0, ev0);
            if (has1) write_state(nHi, nLo, sb1, 128 + se1, ev1);
        }
        tv0 = tn0; tv1 = tn1;
        __syncthreads();
    }

    // Export final hidden state from state buffer (hi+lo reconstruction).
    const uint32_t* fHi = s->sHi[Ssz & 1];
    const uint32_t* fLo = s->sLo[Ssz & 1];
    for (int i = tid; i < NB * Hsz; i += 256) {
        const int b = i >> 7, jj = i & 127;
        const int kp = jj >> 1, hf = jj & 1;
        const float hi = __bfloat162float(__ushort_as_bfloat16(((const uint16_t*)&fHi[b * SROW + kp])[hf]));
        const float lo = __bfloat162float(__ushort_as_bfloat16(((const uint16_t*)&fLo[b * SROW + kp])[hf]));
        g_hfin[(B0 + b) * Hsz + jj] = hi + lo;
    }
}

// ---------------------------------------------------------------------------
// FC epilogue: out[b][n] = h_fin[b] . w_fc[n] + b_fc[n]
// ---------------------------------------------------------------------------
__global__ void fc_kernel(const float* __restrict__ b_fc, float* __restrict__ out) {
    __shared__ float hs[8][Hsz];
    const int tid = threadIdx.x;
    const int n   = blockIdx.x * 128 + tid;
    const int bb  = blockIdx.y * 8;
    for (int i = tid; i < 8 * Hsz; i += 128)
        hs[i >> 7][i & 127] = g_hfin[(bb + (i >> 7)) * Hsz + (i & 127)];
    __syncthreads();
    if (n >= NCLS) return;
    const float bv = b_fc[n];
    float acc[8];
    #pragma unroll
    for (int i = 0; i < 8; i++) acc[i] = bv;
    #pragma unroll 4
    for (int k = 0; k < Hsz; k++) {
        const float w = g_wfcT[k * NCLS + n];
        #pragma unroll
        for (int i = 0; i < 8; i++) acc[i] = fmaf(hs[i][k], w, acc[i]);
    }
    #pragma unroll
    for (int i = 0; i < 8; i++) out[(bb + i) * NCLS + n] = acc[i];
}

extern "C" void kernel_launch(void* const* d_in, const int* in_sizes, int n_in,
                              void* d_out, int out_size) {
    const int*   x    = (const int*)  d_in[0];
    const float* emb  = (const float*)d_in[1];
    const float* w_ih = (const float*)d_in[2];
    const float* w_hh = (const float*)d_in[3];
    const float* b_ih = (const float*)d_in[4];
    const float* b_hh = (const float*)d_in[5];
    const float* w_fc = (const float*)d_in[6];
    const float* b_fc = (const float*)d_in[7];
    float* out = (float*)d_out;

    static bool attr_set = false;
    if (!attr_set) {
        cudaFuncSetAttribute(lstm_kernel, cudaFuncAttributeMaxDynamicSharedMemorySize,
                             (int)sizeof(Smem));
        attr_set = true;
    }

    prep_kernel<<<1000, 256>>>(w_ih, w_hh, b_ih, b_hh, w_fc);
    lstm_kernel<<<NCTA, 256, sizeof(Smem)>>>(x, emb);
    fc_kernel<<<dim3((NCLS + 127) / 128, Bsz / 8), 128>>>(b_fc, out);
}